// round 5
// baseline (speedup 1.0000x reference)
#include <cuda_runtime.h>
#include <math.h>

#define NROWS 65536
#define KDIM  512
#define A3    64
#define CWIN  16
#define DTOW  8
#define PLEN  96

// ---------------- scratch (device globals; no allocations allowed) ----------
__device__ float g_t   [(size_t)NROWS * A3];            // 16 MB
__device__ float g_repT[(size_t)A3 * NROWS];            // 16 MB (k-major)
__device__ float g_h   [(size_t)DTOW * NROWS * A3];     // 128 MB
__device__ float g_y   [(size_t)DTOW * NROWS * PLEN];   // 192 MB
__device__ float g_sum[DTOW * A3];
__device__ float g_sq [DTOW * A3];
__device__ float g_scale[DTOW * A3];
__device__ float g_shift[DTOW * A3];

// ---------------- K1: t = normalize(x @ shuzhihua) ---------------------------
// 128x64 tile / block, 256 threads (16x16), 8x4 micro-tile, BK=32, K=512.
// Double-buffered k-major A smem; B read directly via LDG (L1/L2-hot, 128KB).
__global__ void __launch_bounds__(256) k1_gemm_norm(const float* __restrict__ x,
                                                    const float* __restrict__ w) {
    __shared__ float As_T[2][32][132];   // [buf][k][row]
    __shared__ float rnorm[128];
    const int tid = threadIdx.x;
    const int tx = tid & 15, ty = tid >> 4;
    const int r0 = blockIdx.x * 128;
    const int lrow = tid >> 3, lkq = tid & 7;   // loader coords

    float acc[8][4];
#pragma unroll
    for (int rr = 0; rr < 8; rr++)
#pragma unroll
        for (int cc = 0; cc < 4; cc++) acc[rr][cc] = 0.f;

    // prologue: chunk 0 -> buf 0
    float4 av[4];
#pragma unroll
    for (int i = 0; i < 4; i++)
        av[i] = *(const float4*)&x[(size_t)(r0 + lrow + i * 32) * KDIM + lkq * 4];
#pragma unroll
    for (int i = 0; i < 4; i++) {
        As_T[0][lkq * 4 + 0][lrow + i * 32] = av[i].x;
        As_T[0][lkq * 4 + 1][lrow + i * 32] = av[i].y;
        As_T[0][lkq * 4 + 2][lrow + i * 32] = av[i].z;
        As_T[0][lkq * 4 + 3][lrow + i * 32] = av[i].w;
    }

    for (int c = 0; c < 16; c++) {
        __syncthreads();
        if (c < 15) {
            int k0n = (c + 1) * 32;
#pragma unroll
            for (int i = 0; i < 4; i++)
                av[i] = *(const float4*)&x[(size_t)(r0 + lrow + i * 32) * KDIM + k0n + lkq * 4];
        }
        const float* wb = &w[(size_t)(c * 32) * A3 + tx * 4];
        const int buf = c & 1;
#pragma unroll 8
        for (int k = 0; k < 32; k++) {
            float4 a0 = *(const float4*)&As_T[buf][k][ty * 8];
            float4 a1 = *(const float4*)&As_T[buf][k][ty * 8 + 4];
            float4 bv = *(const float4*)&wb[k * A3];
            float a[8] = {a0.x, a0.y, a0.z, a0.w, a1.x, a1.y, a1.z, a1.w};
            float b[4] = {bv.x, bv.y, bv.z, bv.w};
#pragma unroll
            for (int rr = 0; rr < 8; rr++)
#pragma unroll
                for (int cc = 0; cc < 4; cc++) acc[rr][cc] += a[rr] * b[cc];
        }
        if (c < 15) {
            const int nb = buf ^ 1;
#pragma unroll
            for (int i = 0; i < 4; i++) {
                As_T[nb][lkq * 4 + 0][lrow + i * 32] = av[i].x;
                As_T[nb][lkq * 4 + 1][lrow + i * 32] = av[i].y;
                As_T[nb][lkq * 4 + 2][lrow + i * 32] = av[i].z;
                As_T[nb][lkq * 4 + 3][lrow + i * 32] = av[i].w;
            }
        }
    }
    if (tid < 128) rnorm[tid] = 0.f;
    __syncthreads();
#pragma unroll
    for (int rr = 0; rr < 8; rr++) {
        float p = acc[rr][0] * acc[rr][0] + acc[rr][1] * acc[rr][1]
                + acc[rr][2] * acc[rr][2] + acc[rr][3] * acc[rr][3];
        atomicAdd(&rnorm[ty * 8 + rr], p);
    }
    __syncthreads();
#pragma unroll
    for (int rr = 0; rr < 8; rr++) {
        float s = 1.f / fmaxf(sqrtf(rnorm[ty * 8 + rr]), 1e-12f);
        *(float4*)&g_t[(size_t)(r0 + ty * 8 + rr) * A3 + tx * 4] =
            make_float4(acc[rr][0] * s, acc[rr][1] * s, acc[rr][2] * s, acc[rr][3] * s);
    }
}

// ---------------- K2: windowed FIR; writes g_repT (k-major) + rep_out --------
__global__ void __launch_bounds__(256) k2_window(const float* __restrict__ lw,
                                                 const float* __restrict__ lb,
                                                 float* __restrict__ rep_out) {
    __shared__ float ts[143 * 64];
    __shared__ float lws[16 * 64];
    __shared__ float sb[64];
    const int tid = threadIdx.x;
    const int r0 = blockIdx.x * 128;
    const int base = (r0 >= 15) ? (r0 - 15) : 0;
    const int nrows = r0 + 128 - base;

    if (blockIdx.x == 0) {          // zero BN accumulators (512 entries)
        g_sum[tid] = 0.f; g_sq[tid] = 0.f;
        g_sum[tid + 256] = 0.f; g_sq[tid + 256] = 0.f;
    }

    for (int i = tid; i < nrows * 16; i += 256)
        ((float4*)ts)[i] = *(const float4*)&g_t[(size_t)base * A3 + (size_t)i * 4];
    for (int i = tid; i < 256; i += 256)
        ((float4*)lws)[i] = ((const float4*)lw)[i];
    if (tid < 64) {
        float s = 0.f;
#pragma unroll
        for (int j = 0; j < 16; j++) s += lb[j * 64 + tid];
        sb[tid] = s;
    }
    __syncthreads();

    const int c = tid & 63;
    const int rg = tid >> 6;
    float lwr[16];
#pragma unroll
    for (int j = 0; j < 16; j++) lwr[j] = lws[j * 64 + c];
    const float sbc = sb[c];

    float buf4[4];
    for (int rr = 0; rr < 32; rr++) {
        int i = r0 + rg * 32 + rr;
        float accv = sbc;
        if (i >= 15) {
            int off = i - 15 - base;
#pragma unroll
            for (int j = 0; j < 16; j++) accv += lwr[j] * ts[(off + j) * 64 + c];
        } else {
#pragma unroll
            for (int j = 0; j < 16; j++) {
                int s = (j < i) ? j : i;
                accv += lwr[j] * ts[s * 64 + c];
            }
        }
        buf4[rr & 3] = accv;
        if ((rr & 3) == 3)   // 4 consecutive rows of column c -> contiguous in g_repT
            *(float4*)&g_repT[(size_t)c * NROWS + i - 3] =
                make_float4(buf4[0], buf4[1], buf4[2], buf4[3]);
        if (rep_out) rep_out[(size_t)i * A3 + c] = accv;
    }
}

// ---------------- K3: h[d] = rep @ W1[d] + b1[d]; BN stats -------------------
// Whole K=64 A-tile in smem (single barrier), W1 via LDG (16KB, L1-hot).
__global__ void __launch_bounds__(256) k3_tower1(const float* __restrict__ W1,
                                                 const float* __restrict__ b1) {
    __shared__ float As_T[64][132];
    __shared__ float csum[64];
    __shared__ float csq[64];
    const int tid = threadIdx.x;
    const int tx = tid & 15, ty = tid >> 4;
    const int d = blockIdx.y;
    const int r0 = blockIdx.x * 128;
    if (tid < 64) { csum[tid] = 0.f; csq[tid] = 0.f; }

    float acc[8][4];
#pragma unroll
    for (int rr = 0; rr < 8; rr++)
#pragma unroll
        for (int cc = 0; cc < 4; cc++) acc[rr][cc] = 0.f;

    // A: 64 k x 128 rows from k-major g_repT (coalesced)
#pragma unroll
    for (int i = 0; i < 8; i++) {
        int idx = tid + i * 256;
        int kk = idx >> 5, rq = idx & 31;
        *(float4*)&As_T[kk][rq * 4] =
            *(const float4*)&g_repT[(size_t)kk * NROWS + r0 + rq * 4];
    }
    __syncthreads();

    const float* W1d = W1 + (size_t)d * A3 * A3 + tx * 4;
#pragma unroll 16
    for (int k = 0; k < A3; k++) {
        float4 a0 = *(const float4*)&As_T[k][ty * 8];
        float4 a1 = *(const float4*)&As_T[k][ty * 8 + 4];
        float4 bv = *(const float4*)&W1d[k * A3];
        float a[8] = {a0.x, a0.y, a0.z, a0.w, a1.x, a1.y, a1.z, a1.w};
        float b[4] = {bv.x, bv.y, bv.z, bv.w};
#pragma unroll
        for (int rr = 0; rr < 8; rr++)
#pragma unroll
            for (int cc = 0; cc < 4; cc++) acc[rr][cc] += a[rr] * b[cc];
    }

    float4 bv = *(const float4*)&b1[d * A3 + tx * 4];
    float bb[4] = {bv.x, bv.y, bv.z, bv.w};
    float ls[4] = {0, 0, 0, 0}, lq[4] = {0, 0, 0, 0};
#pragma unroll
    for (int rr = 0; rr < 8; rr++) {
        float v0 = acc[rr][0] + bb[0], v1 = acc[rr][1] + bb[1];
        float v2 = acc[rr][2] + bb[2], v3 = acc[rr][3] + bb[3];
        *(float4*)&g_h[((size_t)d * NROWS + r0 + ty * 8 + rr) * A3 + tx * 4] =
            make_float4(v0, v1, v2, v3);
        ls[0] += v0; lq[0] += v0 * v0; ls[1] += v1; lq[1] += v1 * v1;
        ls[2] += v2; lq[2] += v2 * v2; ls[3] += v3; lq[3] += v3 * v3;
    }
#pragma unroll
    for (int cc = 0; cc < 4; cc++) {
        atomicAdd(&csum[tx * 4 + cc], ls[cc]);
        atomicAdd(&csq [tx * 4 + cc], lq[cc]);
    }
    __syncthreads();
    if (tid < 64) {
        atomicAdd(&g_sum[d * A3 + tid], csum[tid]);
        atomicAdd(&g_sq [d * A3 + tid], csq [tid]);
    }
}

// ---------------- K4: finalize BN -> fused scale/shift -----------------------
__global__ void k4_stats(const float* __restrict__ gamma,
                         const float* __restrict__ beta) {
    int i = threadIdx.x;
    if (i < DTOW * A3) {
        const float inv_n = 1.0f / (float)NROWS;
        float mean = g_sum[i] * inv_n;
        float var  = g_sq[i] * inv_n - mean * mean;
        float is   = rsqrtf(var + 1e-5f);
        float sc   = is * gamma[i];
        g_scale[i] = sc;
        g_shift[i] = beta[i] - mean * sc;
    }
}

// ---------------- K5: y[d] = elu(norm(h[d])) @ W2[d] + b2[d] -> g_y ----------
// Whole K=64 h-tile in smem (fused affine+ELU), W2 via LDG (24.6KB, L1-hot).
__global__ void __launch_bounds__(256) k5_tower2(const float* __restrict__ W2,
                                                 const float* __restrict__ b2) {
    __shared__ float hs_T[64][132];
    const int tid = threadIdx.x;
    const int tx = tid & 15, ty = tid >> 4;
    const int d = blockIdx.y;
    const int r0 = blockIdx.x * 128;

    float acc[8][6];
#pragma unroll
    for (int rr = 0; rr < 8; rr++)
#pragma unroll
        for (int cc = 0; cc < 6; cc++) acc[rr][cc] = 0.f;

    // h tile: 128 rows x 64 k, affine+ELU fused, stored k-major
#pragma unroll
    for (int i = 0; i < 8; i++) {
        int idx = tid + i * 256;
        int row = idx >> 4, kq = idx & 15;
        float4 v  = *(const float4*)&g_h[((size_t)d * NROWS + r0 + row) * A3 + kq * 4];
        float4 sc = *(const float4*)&g_scale[d * A3 + kq * 4];
        float4 sh = *(const float4*)&g_shift[d * A3 + kq * 4];
        float t0 = v.x * sc.x + sh.x; t0 = t0 > 0.f ? t0 : expm1f(t0);
        float t1 = v.y * sc.y + sh.y; t1 = t1 > 0.f ? t1 : expm1f(t1);
        float t2 = v.z * sc.z + sh.z; t2 = t2 > 0.f ? t2 : expm1f(t2);
        float t3 = v.w * sc.w + sh.w; t3 = t3 > 0.f ? t3 : expm1f(t3);
        hs_T[kq * 4 + 0][row] = t0; hs_T[kq * 4 + 1][row] = t1;
        hs_T[kq * 4 + 2][row] = t2; hs_T[kq * 4 + 3][row] = t3;
    }
    __syncthreads();

    const float* W2d = W2 + (size_t)d * A3 * PLEN + tx * 6;
#pragma unroll 16
    for (int k = 0; k < A3; k++) {
        float4 a0 = *(const float4*)&hs_T[k][ty * 8];
        float4 a1 = *(const float4*)&hs_T[k][ty * 8 + 4];
        float2 b0 = *(const float2*)&W2d[k * PLEN];
        float2 b1v = *(const float2*)&W2d[k * PLEN + 2];
        float2 b2v = *(const float2*)&W2d[k * PLEN + 4];
        float a[8] = {a0.x, a0.y, a0.z, a0.w, a1.x, a1.y, a1.z, a1.w};
        float b[6] = {b0.x, b0.y, b1v.x, b1v.y, b2v.x, b2v.y};
#pragma unroll
        for (int rr = 0; rr < 8; rr++)
#pragma unroll
            for (int cc = 0; cc < 6; cc++) acc[rr][cc] += a[rr] * b[cc];
    }

    float bb[6];
#pragma unroll
    for (int cc = 0; cc < 6; cc++) bb[cc] = b2[d * PLEN + tx * 6 + cc];
#pragma unroll
    for (int rr = 0; rr < 8; rr++) {
        size_t rowoff = ((size_t)d * NROWS + r0 + ty * 8 + rr) * PLEN;
#pragma unroll
        for (int cc = 0; cc < 6; cc++)
            g_y[rowoff + tx * 6 + cc] = acc[rr][cc] + bb[cc];
    }
}

// ---------------- K6: out[n, p*8+d] = g_y[d][n][p] ---------------------------
__global__ void __launch_bounds__(256) k6_interleave(float* __restrict__ out) {
    const size_t M = (size_t)NROWS * PLEN;
    size_t g = (size_t)blockIdx.x * 256 + threadIdx.x;
    float v[8];
#pragma unroll
    for (int d = 0; d < 8; d++) v[d] = g_y[(size_t)d * M + g];
    float4* o = (float4*)out;
    o[2 * g]     = make_float4(v[0], v[1], v[2], v[3]);
    o[2 * g + 1] = make_float4(v[4], v[5], v[6], v[7]);
}

// ---------------- launch ------------------------------------------------------
extern "C" void kernel_launch(void* const* d_in, const int* in_sizes, int n_in,
                              void* d_out, int out_size) {
    const float* x     = (const float*)d_in[0];
    const float* shu   = (const float*)d_in[1];
    const float* lw    = (const float*)d_in[2];
    const float* lb    = (const float*)d_in[3];
    const float* W1    = (const float*)d_in[4];
    const float* b1    = (const float*)d_in[5];
    const float* gamma = (const float*)d_in[6];
    const float* beta  = (const float*)d_in[7];
    const float* W2    = (const float*)d_in[8];
    const float* b2    = (const float*)d_in[9];
    float* out = (float*)d_out;

    float* rep_out = ((size_t)out_size >= (size_t)NROWS * (PLEN * DTOW + A3))
                         ? out + (size_t)NROWS * PLEN * DTOW
                         : nullptr;

    k1_gemm_norm<<<NROWS / 128, 256>>>(x, shu);
    k2_window<<<NROWS / 128, 256>>>(lw, lb, rep_out);   // also zeros BN accums, writes g_repT
    k3_tower1<<<dim3(NROWS / 128, DTOW), 256>>>(W1, b1);
    k4_stats<<<1, 512>>>(gamma, beta);
    k5_tower2<<<dim3(NROWS / 128, DTOW), 256>>>(W2, b2);
    k6_interleave<<<(NROWS * PLEN) / 256, 256>>>(out);
}

// round 8
// speedup vs baseline: 1.0494x; 1.0494x over previous
#include <cuda_runtime.h>
#include <cuda_bf16.h>
#include <math.h>
#include <cstdint>

#define NROWS 65536
#define KDIM  512
#define A3    64
#define CWIN  16
#define DTOW  8
#define PLEN  96

// ---------------- scratch (device globals; no allocations allowed) ----------
__device__ float g_t   [(size_t)NROWS * A3];
__device__ float g_rep [(size_t)NROWS * A3];
__device__ float g_repT[(size_t)A3 * NROWS];
__device__ float g_h   [(size_t)DTOW * NROWS * A3];
__device__ float g_y   [(size_t)DTOW * NROWS * PLEN];   // [d][n][p] row-major
__device__ float g_sum[DTOW * A3];
__device__ float g_sq [DTOW * A3];
__device__ float g_scale[DTOW * A3];
__device__ float g_shift[DTOW * A3];

// ---------------- mma.sync helper (HMMA, baseline PTX, works on sm_103) -----
__device__ __forceinline__ void mma16816(float* c, const uint32_t* a, const uint32_t* b) {
    asm volatile(
        "mma.sync.aligned.m16n8k16.row.col.f32.bf16.bf16.f32 "
        "{%0,%1,%2,%3}, {%4,%5,%6,%7}, {%8,%9}, {%0,%1,%2,%3};"
        : "+f"(c[0]), "+f"(c[1]), "+f"(c[2]), "+f"(c[3])
        : "r"(a[0]), "r"(a[1]), "r"(a[2]), "r"(a[3]), "r"(b[0]), "r"(b[1]));
}
__device__ __forceinline__ uint32_t pack_bf16x2(float lo, float hi_) {
    __nv_bfloat16 a = __float2bfloat16(lo), b = __float2bfloat16(hi_);
    return ((uint32_t)__bfloat16_as_ushort(b) << 16) | (uint32_t)__bfloat16_as_ushort(a);
}

// ---------------- K1: t = normalize(x @ shuzhihua)  [Round-4 form] -----------
__global__ void __launch_bounds__(256) k1_gemm_norm(const float* __restrict__ x,
                                                    const float* __restrict__ w) {
    __shared__ float As_T[32][132];
    __shared__ float Bs[32][64];
    __shared__ float rnorm[128];
    const int tid = threadIdx.x;
    const int tx = tid & 15, ty = tid >> 4;
    const int r0 = blockIdx.x * 128;

    float acc[8][4];
#pragma unroll
    for (int rr = 0; rr < 8; rr++)
#pragma unroll
        for (int cc = 0; cc < 4; cc++) acc[rr][cc] = 0.f;

    for (int k0 = 0; k0 < KDIM; k0 += 32) {
#pragma unroll
        for (int i = 0; i < 4; i++) {
            int idx = tid + i * 256;
            int row = idx >> 3, kq = idx & 7;
            float4 v = *(const float4*)&x[(size_t)(r0 + row) * KDIM + k0 + kq * 4];
            As_T[kq * 4 + 0][row] = v.x; As_T[kq * 4 + 1][row] = v.y;
            As_T[kq * 4 + 2][row] = v.z; As_T[kq * 4 + 3][row] = v.w;
        }
#pragma unroll
        for (int i = 0; i < 2; i++) {
            int idx = tid + i * 256;
            int kk = idx >> 4, cq = idx & 15;
            *(float4*)&Bs[kk][cq * 4] =
                *(const float4*)&w[(size_t)(k0 + kk) * A3 + cq * 4];
        }
        __syncthreads();
#pragma unroll 8
        for (int k = 0; k < 32; k++) {
            float4 a0 = *(const float4*)&As_T[k][ty * 8];
            float4 a1 = *(const float4*)&As_T[k][ty * 8 + 4];
            float4 bv = *(const float4*)&Bs[k][tx * 4];
            float a[8] = {a0.x, a0.y, a0.z, a0.w, a1.x, a1.y, a1.z, a1.w};
            float b[4] = {bv.x, bv.y, bv.z, bv.w};
#pragma unroll
            for (int rr = 0; rr < 8; rr++)
#pragma unroll
                for (int cc = 0; cc < 4; cc++) acc[rr][cc] += a[rr] * b[cc];
        }
        __syncthreads();
    }
    if (tid < 128) rnorm[tid] = 0.f;
    __syncthreads();
#pragma unroll
    for (int rr = 0; rr < 8; rr++) {
        float p = acc[rr][0] * acc[rr][0] + acc[rr][1] * acc[rr][1]
                + acc[rr][2] * acc[rr][2] + acc[rr][3] * acc[rr][3];
        atomicAdd(&rnorm[ty * 8 + rr], p);
    }
    __syncthreads();
#pragma unroll
    for (int rr = 0; rr < 8; rr++) {
        float s = 1.f / fmaxf(sqrtf(rnorm[ty * 8 + rr]), 1e-12f);
        *(float4*)&g_t[(size_t)(r0 + ty * 8 + rr) * A3 + tx * 4] =
            make_float4(acc[rr][0] * s, acc[rr][1] * s, acc[rr][2] * s, acc[rr][3] * s);
    }
}

// ---------------- K2: windowed FIR  [Round-4 form] ----------------------------
__global__ void __launch_bounds__(256) k2_window(const float* __restrict__ lw,
                                                 const float* __restrict__ lb,
                                                 float* __restrict__ rep_out) {
    __shared__ float ts[143 * 64];
    __shared__ float lws[16 * 64];
    __shared__ float sb[64];
    const int tid = threadIdx.x;
    const int r0 = blockIdx.x * 128;
    const int base = (r0 >= 15) ? (r0 - 15) : 0;
    const int nrows = r0 + 128 - base;

    for (int i = tid; i < nrows * 16; i += 256)
        ((float4*)ts)[i] = *(const float4*)&g_t[(size_t)base * A3 + (size_t)i * 4];
    for (int i = tid; i < 256; i += 256)
        ((float4*)lws)[i] = ((const float4*)lw)[i];
    if (tid < 64) {
        float s = 0.f;
#pragma unroll
        for (int j = 0; j < 16; j++) s += lb[j * 64 + tid];
        sb[tid] = s;
    }
    __syncthreads();

    const int c = tid & 63;
    const int rg = tid >> 6;
    float lwr[16];
#pragma unroll
    for (int j = 0; j < 16; j++) lwr[j] = lws[j * 64 + c];
    const float sbc = sb[c];

    for (int rr = 0; rr < 32; rr++) {
        int i = r0 + rg * 32 + rr;
        float accv = sbc;
        if (i >= 15) {
            int off = i - 15 - base;
#pragma unroll
            for (int j = 0; j < 16; j++) accv += lwr[j] * ts[(off + j) * 64 + c];
        } else {
#pragma unroll
            for (int j = 0; j < 16; j++) {
                int s = (j < i) ? j : i;
                accv += lwr[j] * ts[s * 64 + c];
            }
        }
        g_rep[(size_t)i * A3 + c] = accv;
        if (rep_out) rep_out[(size_t)i * A3 + c] = accv;
    }
}

// ---------------- K2t: rep -> rep_T + BN accum zeroing  [Round-4 form] -------
__global__ void __launch_bounds__(256) k2t_transpose() {
    __shared__ float tile[32][33];
    const int tx = threadIdx.x & 31, ty = threadIdx.x >> 5;
    const int r0 = blockIdx.x * 32;
    const int c0 = blockIdx.y * 32;
    if (blockIdx.x == 0 && blockIdx.y == 0 && threadIdx.x < 256) {
        int i2 = threadIdx.x;
        g_sum[i2] = 0.f; g_sq[i2] = 0.f;
        g_sum[i2 + 256] = 0.f; g_sq[i2 + 256] = 0.f;
    }
#pragma unroll
    for (int j = 0; j < 32; j += 8)
        tile[ty + j][tx] = g_rep[(size_t)(r0 + ty + j) * A3 + c0 + tx];
    __syncthreads();
#pragma unroll
    for (int j = 0; j < 32; j += 8)
        g_repT[(size_t)(c0 + ty + j) * NROWS + r0 + tx] = tile[tx][ty + j];
}

// ---------------- K3: h = rep @ W1 + b1; BN stats  [Round-4 form] ------------
__global__ void __launch_bounds__(256) k3_tower1(const float* __restrict__ W1,
                                                 const float* __restrict__ b1) {
    __shared__ float As_T[32][132];
    __shared__ float Bs[32][64];
    __shared__ float csum[64];
    __shared__ float csq[64];
    const int tid = threadIdx.x;
    const int tx = tid & 15, ty = tid >> 4;
    const int d = blockIdx.y;
    const int r0 = blockIdx.x * 128;
    if (tid < 64) { csum[tid] = 0.f; csq[tid] = 0.f; }

    float acc[8][4];
#pragma unroll
    for (int rr = 0; rr < 8; rr++)
#pragma unroll
        for (int cc = 0; cc < 4; cc++) acc[rr][cc] = 0.f;

    const float* W1d = W1 + (size_t)d * A3 * A3;
    for (int k0 = 0; k0 < A3; k0 += 32) {
#pragma unroll
        for (int i = 0; i < 4; i++) {
            int idx = tid + i * 256;
            int kk = idx >> 5, rq = idx & 31;
            *(float4*)&As_T[kk][rq * 4] =
                *(const float4*)&g_repT[(size_t)(k0 + kk) * NROWS + r0 + rq * 4];
        }
#pragma unroll
        for (int i = 0; i < 2; i++) {
            int idx = tid + i * 256;
            int kk = idx >> 4, cq = idx & 15;
            *(float4*)&Bs[kk][cq * 4] =
                *(const float4*)&W1d[(size_t)(k0 + kk) * A3 + cq * 4];
        }
        __syncthreads();
#pragma unroll 8
        for (int k = 0; k < 32; k++) {
            float4 a0 = *(const float4*)&As_T[k][ty * 8];
            float4 a1 = *(const float4*)&As_T[k][ty * 8 + 4];
            float4 bv = *(const float4*)&Bs[k][tx * 4];
            float a[8] = {a0.x, a0.y, a0.z, a0.w, a1.x, a1.y, a1.z, a1.w};
            float b[4] = {bv.x, bv.y, bv.z, bv.w};
#pragma unroll
            for (int rr = 0; rr < 8; rr++)
#pragma unroll
                for (int cc = 0; cc < 4; cc++) acc[rr][cc] += a[rr] * b[cc];
        }
        __syncthreads();
    }
    float4 bv = *(const float4*)&b1[d * A3 + tx * 4];
    float bb[4] = {bv.x, bv.y, bv.z, bv.w};
    float ls[4] = {0, 0, 0, 0}, lq[4] = {0, 0, 0, 0};
#pragma unroll
    for (int rr = 0; rr < 8; rr++) {
        float v0 = acc[rr][0] + bb[0], v1 = acc[rr][1] + bb[1];
        float v2 = acc[rr][2] + bb[2], v3 = acc[rr][3] + bb[3];
        *(float4*)&g_h[((size_t)d * NROWS + r0 + ty * 8 + rr) * A3 + tx * 4] =
            make_float4(v0, v1, v2, v3);
        ls[0] += v0; lq[0] += v0 * v0; ls[1] += v1; lq[1] += v1 * v1;
        ls[2] += v2; lq[2] += v2 * v2; ls[3] += v3; lq[3] += v3 * v3;
    }
#pragma unroll
    for (int cc = 0; cc < 4; cc++) {
        atomicAdd(&csum[tx * 4 + cc], ls[cc]);
        atomicAdd(&csq [tx * 4 + cc], lq[cc]);
    }
    __syncthreads();
    if (tid < 64) {
        atomicAdd(&g_sum[d * A3 + tid], csum[tid]);
        atomicAdd(&g_sq [d * A3 + tid], csq [tid]);
    }
}

// ---------------- K4: finalize BN -------------------------------------------
__global__ void k4_stats(const float* __restrict__ gamma,
                         const float* __restrict__ beta) {
    int i = threadIdx.x;
    if (i < DTOW * A3) {
        const float inv_n = 1.0f / (float)NROWS;
        float mean = g_sum[i] * inv_n;
        float var  = g_sq[i] * inv_n - mean * mean;
        float is   = rsqrtf(var + 1e-5f);
        float sc   = is * gamma[i];
        g_scale[i] = sc;
        g_shift[i] = beta[i] - mean * sc;
    }
}

// ---------------- K5 (mma.sync bf16): y = elu(bn(h)) @ W2 + b2 ---------------
// 3-way bf16 split, fp32 register accumulators: C = Ah*Bh + Al*Bh + Ah*Bl.
// Block: 128(m) x 96(n) tile, 8 warps = 4(m) x 2(n), warp tile 32x48.
// Smem: hi/lo bf16-pairs interleaved as uint2; one LDS.64 -> hi+lo fragment regs.
__global__ void __launch_bounds__(256) k5_tower2_mma(const float* __restrict__ W2,
                                                     const float* __restrict__ b2) {
    __shared__ uint2 As[128][17];   // [row][kpair] chunk of 32 k (16 kpairs, pad 17)
    __shared__ uint2 Bs[96][17];    // [n]  [kpair]
    const int tid = threadIdx.x;
    const int wid = tid >> 5, lane = tid & 31;
    const int d = blockIdx.y;
    const int r0 = blockIdx.x * 128;
    const int mwarp = (wid & 3) * 32;   // warp row base within tile
    const int nwarp = (wid >> 2) * 48;  // warp col base within tile

    float acc[12][4];
#pragma unroll
    for (int f = 0; f < 12; f++)
#pragma unroll
        for (int j = 0; j < 4; j++) acc[f][j] = 0.f;

    const float* hbase = g_h + ((size_t)d * NROWS + r0) * A3;
    const float* W2d = W2 + (size_t)d * A3 * PLEN;

    for (int c = 0; c < 2; c++) {         // two K-chunks of 32
        const int k0 = c * 32;
        __syncthreads();
        // ---- A fill: affine+ELU fused, hi/lo split, 128x16 kpairs -----------
        for (int i = tid; i < 128 * 16; i += 256) {
            int r = i >> 4, kp = i & 15;
            int k = k0 + kp * 2;
            float2 v = *(const float2*)&hbase[(size_t)r * A3 + k];
            float t0 = fmaf(v.x, g_scale[d * A3 + k],     g_shift[d * A3 + k]);
            float t1 = fmaf(v.y, g_scale[d * A3 + k + 1], g_shift[d * A3 + k + 1]);
            t0 = t0 > 0.f ? t0 : expm1f(t0);
            t1 = t1 > 0.f ? t1 : expm1f(t1);
            float h0 = __bfloat162float(__float2bfloat16(t0));
            float h1 = __bfloat162float(__float2bfloat16(t1));
            As[r][kp] = make_uint2(pack_bf16x2(h0, h1),
                                   pack_bf16x2(t0 - h0, t1 - h1));
        }
        // ---- B fill: Bs[n][kp] from W2[k][n], hi/lo split -------------------
        for (int i = tid; i < PLEN * 16; i += 256) {
            int n = i % PLEN, kp = i / PLEN;
            int k = k0 + kp * 2;
            float w0 = W2d[(size_t)k * PLEN + n];
            float w1 = W2d[(size_t)(k + 1) * PLEN + n];
            float h0 = __bfloat162float(__float2bfloat16(w0));
            float h1 = __bfloat162float(__float2bfloat16(w1));
            Bs[n][kp] = make_uint2(pack_bf16x2(h0, h1),
                                   pack_bf16x2(w0 - h0, w1 - h1));
        }
        __syncthreads();
        // ---- mainloop: 2 ksteps of 16 ---------------------------------------
#pragma unroll
        for (int s = 0; s < 2; s++) {
            const int kb = s * 8;
            uint32_t ah[2][4], al[2][4];
#pragma unroll
            for (int mi = 0; mi < 2; mi++) {
                int r = mwarp + mi * 16 + (lane >> 2);
                uint2 q0 = As[r][kb + (lane & 3)];
                uint2 q1 = As[r + 8][kb + (lane & 3)];
                uint2 q2 = As[r][kb + (lane & 3) + 4];
                uint2 q3 = As[r + 8][kb + (lane & 3) + 4];
                ah[mi][0] = q0.x; ah[mi][1] = q1.x; ah[mi][2] = q2.x; ah[mi][3] = q3.x;
                al[mi][0] = q0.y; al[mi][1] = q1.y; al[mi][2] = q2.y; al[mi][3] = q3.y;
            }
#pragma unroll
            for (int ni = 0; ni < 6; ni++) {
                int n = nwarp + ni * 8 + (lane >> 2);
                uint2 p0 = Bs[n][kb + (lane & 3)];
                uint2 p1 = Bs[n][kb + (lane & 3) + 4];
                uint32_t bh[2] = {p0.x, p1.x};
                uint32_t bl[2] = {p0.y, p1.y};
#pragma unroll
                for (int mi = 0; mi < 2; mi++) {
                    float* C = acc[mi * 6 + ni];
                    mma16816(C, ah[mi], bh);
                    mma16816(C, al[mi], bh);
                    mma16816(C, ah[mi], bl);
                }
            }
        }
    }
    // ---- epilogue: +b2, direct STG.64 (fills whole 32B sectors) --------------
    float* ybase = g_y + ((size_t)d * NROWS + r0) * PLEN;
#pragma unroll
    for (int mi = 0; mi < 2; mi++) {
        int r = mwarp + mi * 16 + (lane >> 2);
#pragma unroll
        for (int ni = 0; ni < 6; ni++) {
            int p = nwarp + ni * 8 + (lane & 3) * 2;
            float bb0 = b2[d * PLEN + p], bb1 = b2[d * PLEN + p + 1];
            const float* C = acc[mi * 6 + ni];
            *(float2*)&ybase[(size_t)r * PLEN + p] =
                make_float2(C[0] + bb0, C[1] + bb1);
            *(float2*)&ybase[(size_t)(r + 8) * PLEN + p] =
                make_float2(C[2] + bb0, C[3] + bb1);
        }
    }
}

// ---------------- K6: out[n, p*8+d] = g_y[d][n][p]  [Round-4 form] -----------
__global__ void __launch_bounds__(256) k6_interleave(float* __restrict__ out) {
    const size_t M = (size_t)NROWS * PLEN;
    size_t g = (size_t)blockIdx.x * 256 + threadIdx.x;
    float v[8];
#pragma unroll
    for (int d = 0; d < 8; d++) v[d] = g_y[(size_t)d * M + g];
    float4* o = (float4*)out;
    o[2 * g]     = make_float4(v[0], v[1], v[2], v[3]);
    o[2 * g + 1] = make_float4(v[4], v[5], v[6], v[7]);
}

// ---------------- launch ------------------------------------------------------
extern "C" void kernel_launch(void* const* d_in, const int* in_sizes, int n_in,
                              void* d_out, int out_size) {
    const float* x     = (const float*)d_in[0];
    const float* shu   = (const float*)d_in[1];
    const float* lw    = (const float*)d_in[2];
    const float* lb    = (const float*)d_in[3];
    const float* W1    = (const float*)d_in[4];
    const float* b1    = (const float*)d_in[5];
    const float* gamma = (const float*)d_in[6];
    const float* beta  = (const float*)d_in[7];
    const float* W2    = (const float*)d_in[8];
    const float* b2    = (const float*)d_in[9];
    float* out = (float*)d_out;

    float* rep_out = ((size_t)out_size >= (size_t)NROWS * (PLEN * DTOW + A3))
                         ? out + (size_t)NROWS * PLEN * DTOW
                         : nullptr;

    k1_gemm_norm<<<NROWS / 128, 256>>>(x, shu);
    k2_window<<<NROWS / 128, 256>>>(lw, lb, rep_out);
    k2t_transpose<<<dim3(NROWS / 32, A3 / 32), 256>>>();
    k3_tower1<<<dim3(NROWS / 128, DTOW), 256>>>(W1, b1);
    k4_stats<<<1, 512>>>(gamma, beta);
    k5_tower2_mma<<<dim3(NROWS / 128, DTOW), 256>>>(W2, b2);
    k6_interleave<<<(NROWS * PLEN) / 256, 256>>>(out);
}

// round 9
// speedup vs baseline: 1.4573x; 1.3886x over previous
#include <cuda_runtime.h>
#include <cuda_bf16.h>
#include <math.h>
#include <cstdint>

#define NROWS 65536
#define KDIM  512
#define A3    64
#define CWIN  16
#define DTOW  8
#define PLEN  96

// ---------------- scratch (device globals; no allocations allowed) ----------
__device__ float g_t   [(size_t)NROWS * A3];
__device__ float g_rep [(size_t)NROWS * A3];
__device__ float g_h   [(size_t)DTOW * NROWS * A3];
__device__ float g_y   [(size_t)DTOW * NROWS * PLEN];   // [d][n][p] row-major
__device__ float g_sum[DTOW * A3];
__device__ float g_sq [DTOW * A3];
__device__ float g_scale[DTOW * A3];
__device__ float g_shift[DTOW * A3];

// ---------------- mma.sync helper (HMMA, baseline PTX) -----------------------
__device__ __forceinline__ void mma16816(float* c, const uint32_t* a, const uint32_t* b) {
    asm volatile(
        "mma.sync.aligned.m16n8k16.row.col.f32.bf16.bf16.f32 "
        "{%0,%1,%2,%3}, {%4,%5,%6,%7}, {%8,%9}, {%0,%1,%2,%3};"
        : "+f"(c[0]), "+f"(c[1]), "+f"(c[2]), "+f"(c[3])
        : "r"(a[0]), "r"(a[1]), "r"(a[2]), "r"(a[3]), "r"(b[0]), "r"(b[1]));
}
__device__ __forceinline__ uint32_t pack_bf16x2(float lo, float hi_) {
    __nv_bfloat16 a = __float2bfloat16(lo), b = __float2bfloat16(hi_);
    return ((uint32_t)__bfloat16_as_ushort(b) << 16) | (uint32_t)__bfloat16_as_ushort(a);
}

// ---------------- K1: t = normalize(x @ shuzhihua)  [Round-4 scalar] ---------
__global__ void __launch_bounds__(256) k1_gemm_norm(const float* __restrict__ x,
                                                    const float* __restrict__ w) {
    __shared__ float As_T[32][132];
    __shared__ float Bs[32][64];
    __shared__ float rnorm[128];
    const int tid = threadIdx.x;
    const int tx = tid & 15, ty = tid >> 4;
    const int r0 = blockIdx.x * 128;

    float acc[8][4];
#pragma unroll
    for (int rr = 0; rr < 8; rr++)
#pragma unroll
        for (int cc = 0; cc < 4; cc++) acc[rr][cc] = 0.f;

    for (int k0 = 0; k0 < KDIM; k0 += 32) {
#pragma unroll
        for (int i = 0; i < 4; i++) {
            int idx = tid + i * 256;
            int row = idx >> 3, kq = idx & 7;
            float4 v = *(const float4*)&x[(size_t)(r0 + row) * KDIM + k0 + kq * 4];
            As_T[kq * 4 + 0][row] = v.x; As_T[kq * 4 + 1][row] = v.y;
            As_T[kq * 4 + 2][row] = v.z; As_T[kq * 4 + 3][row] = v.w;
        }
#pragma unroll
        for (int i = 0; i < 2; i++) {
            int idx = tid + i * 256;
            int kk = idx >> 4, cq = idx & 15;
            *(float4*)&Bs[kk][cq * 4] =
                *(const float4*)&w[(size_t)(k0 + kk) * A3 + cq * 4];
        }
        __syncthreads();
#pragma unroll 8
        for (int k = 0; k < 32; k++) {
            float4 a0 = *(const float4*)&As_T[k][ty * 8];
            float4 a1 = *(const float4*)&As_T[k][ty * 8 + 4];
            float4 bv = *(const float4*)&Bs[k][tx * 4];
            float a[8] = {a0.x, a0.y, a0.z, a0.w, a1.x, a1.y, a1.z, a1.w};
            float b[4] = {bv.x, bv.y, bv.z, bv.w};
#pragma unroll
            for (int rr = 0; rr < 8; rr++)
#pragma unroll
                for (int cc = 0; cc < 4; cc++) acc[rr][cc] += a[rr] * b[cc];
        }
        __syncthreads();
    }
    if (tid < 128) rnorm[tid] = 0.f;
    __syncthreads();
#pragma unroll
    for (int rr = 0; rr < 8; rr++) {
        float p = acc[rr][0] * acc[rr][0] + acc[rr][1] * acc[rr][1]
                + acc[rr][2] * acc[rr][2] + acc[rr][3] * acc[rr][3];
        atomicAdd(&rnorm[ty * 8 + rr], p);
    }
    __syncthreads();
#pragma unroll
    for (int rr = 0; rr < 8; rr++) {
        float s = 1.f / fmaxf(sqrtf(rnorm[ty * 8 + rr]), 1e-12f);
        *(float4*)&g_t[(size_t)(r0 + ty * 8 + rr) * A3 + tx * 4] =
            make_float4(acc[rr][0] * s, acc[rr][1] * s, acc[rr][2] * s, acc[rr][3] * s);
    }
}

// ---------------- K2: windowed FIR + BN accum zeroing ------------------------
__global__ void __launch_bounds__(256) k2_window(const float* __restrict__ lw,
                                                 const float* __restrict__ lb,
                                                 float* __restrict__ rep_out) {
    __shared__ float ts[143 * 64];
    __shared__ float lws[16 * 64];
    __shared__ float sb[64];
    const int tid = threadIdx.x;
    const int r0 = blockIdx.x * 128;
    const int base = (r0 >= 15) ? (r0 - 15) : 0;
    const int nrows = r0 + 128 - base;

    if (blockIdx.x == 0) {
        g_sum[tid] = 0.f; g_sq[tid] = 0.f;
        g_sum[tid + 256] = 0.f; g_sq[tid + 256] = 0.f;
    }

    for (int i = tid; i < nrows * 16; i += 256)
        ((float4*)ts)[i] = *(const float4*)&g_t[(size_t)base * A3 + (size_t)i * 4];
    for (int i = tid; i < 256; i += 256)
        ((float4*)lws)[i] = ((const float4*)lw)[i];
    if (tid < 64) {
        float s = 0.f;
#pragma unroll
        for (int j = 0; j < 16; j++) s += lb[j * 64 + tid];
        sb[tid] = s;
    }
    __syncthreads();

    const int c = tid & 63;
    const int rg = tid >> 6;
    float lwr[16];
#pragma unroll
    for (int j = 0; j < 16; j++) lwr[j] = lws[j * 64 + c];
    const float sbc = sb[c];

    for (int rr = 0; rr < 32; rr++) {
        int i = r0 + rg * 32 + rr;
        float accv = sbc;
        if (i >= 15) {
            int off = i - 15 - base;
#pragma unroll
            for (int j = 0; j < 16; j++) accv += lwr[j] * ts[(off + j) * 64 + c];
        } else {
#pragma unroll
            for (int j = 0; j < 16; j++) {
                int s = (j < i) ? j : i;
                accv += lwr[j] * ts[s * 64 + c];
            }
        }
        g_rep[(size_t)i * A3 + c] = accv;
        if (rep_out) rep_out[(size_t)i * A3 + c] = accv;
    }
}

// ---------------- K3 (mma): h = rep @ W1 + b1; BN stats ----------------------
// Canonical-fragment smem: one LDS.128 = full A frag, one LDS.64 = full B frag.
// 3-pass bf16 split (validated R8). 8 warps = 4(m)x2(n); warp tile 32x32.
__global__ void __launch_bounds__(256) k3_tower1_mma(const float* __restrict__ W1,
                                                     const float* __restrict__ b1) {
    __shared__ uint32_t cA[2][8][2][32][4];   // [comp][tile_r][tile_k][lane][reg] 16KB
    __shared__ uint32_t cB[2][8][2][32][2];   // [comp][tile_n][tile_k][lane][reg]  8KB
    __shared__ float csum[64], csq[64];
    const int tid = threadIdx.x, wid = tid >> 5, lane = tid & 31;
    const int d = blockIdx.y;
    const int r0 = blockIdx.x * 128;
    const int mw = wid & 3, nw = wid >> 2;
    if (tid < 64) { csum[tid] = 0.f; csq[tid] = 0.f; }

    float accm[2][4][4];
#pragma unroll
    for (int mi = 0; mi < 2; mi++)
#pragma unroll
        for (int ni = 0; ni < 4; ni++)
#pragma unroll
            for (int j = 0; j < 4; j++) accm[mi][ni][j] = 0.f;

    const float* abase = g_rep + (size_t)r0 * A3;
    const float* W1d = W1 + (size_t)d * A3 * A3;

    for (int c = 0; c < 2; c++) {
        const int k0 = c * 32;
        __syncthreads();
        // A fill: 128 rows x 16 kpairs
#pragma unroll
        for (int it = 0; it < 8; it++) {
            int i = tid + it * 256;
            int r = i >> 4, kp = i & 15;
            int kg = k0 + kp * 2;
            float2 v = *(const float2*)&abase[(size_t)r * A3 + kg];
            float h0 = __bfloat162float(__float2bfloat16(v.x));
            float h1 = __bfloat162float(__float2bfloat16(v.y));
            int ln = (r & 7) * 4 + (kp & 3);
            int rg = ((r >> 3) & 1) | ((kp & 4) >> 1);
            cA[0][r >> 4][kp >> 3][ln][rg] = pack_bf16x2(h0, h1);
            cA[1][r >> 4][kp >> 3][ln][rg] = pack_bf16x2(v.x - h0, v.y - h1);
        }
        // B fill: 64 n x 16 kpairs (W1 is [k][n])
#pragma unroll
        for (int it = 0; it < 4; it++) {
            int i = tid + it * 256;
            int n = i & 63, kp = i >> 6;
            int kg = k0 + kp * 2;
            float w0 = W1d[(size_t)kg * A3 + n];
            float w1 = W1d[(size_t)(kg + 1) * A3 + n];
            float h0 = __bfloat162float(__float2bfloat16(w0));
            float h1 = __bfloat162float(__float2bfloat16(w1));
            int ln = (n & 7) * 4 + (kp & 3);
            int rg = (kp & 4) >> 2;
            cB[0][n >> 3][kp >> 3][ln][rg] = pack_bf16x2(h0, h1);
            cB[1][n >> 3][kp >> 3][ln][rg] = pack_bf16x2(w0 - h0, w1 - h1);
        }
        __syncthreads();
#pragma unroll
        for (int tk = 0; tk < 2; tk++) {
            uint32_t ah0[4], ah1[4], al0[4], al1[4];
            *(uint4*)ah0 = *(const uint4*)cA[0][mw * 2 + 0][tk][lane];
            *(uint4*)ah1 = *(const uint4*)cA[0][mw * 2 + 1][tk][lane];
            *(uint4*)al0 = *(const uint4*)cA[1][mw * 2 + 0][tk][lane];
            *(uint4*)al1 = *(const uint4*)cA[1][mw * 2 + 1][tk][lane];
#pragma unroll
            for (int ni = 0; ni < 4; ni++) {
                uint32_t bh[2], bl[2];
                *(uint2*)bh = *(const uint2*)cB[0][nw * 4 + ni][tk][lane];
                *(uint2*)bl = *(const uint2*)cB[1][nw * 4 + ni][tk][lane];
                mma16816(accm[0][ni], ah0, bh);
                mma16816(accm[1][ni], ah1, bh);
                mma16816(accm[0][ni], al0, bh);
                mma16816(accm[1][ni], al1, bh);
                mma16816(accm[0][ni], ah0, bl);
                mma16816(accm[1][ni], ah1, bl);
            }
        }
    }
    // epilogue: +b1, store h, BN stats (shfl-reduce over the 8 lanes per col)
    float* hb = g_h + ((size_t)d * NROWS + r0) * A3;
#pragma unroll
    for (int ni = 0; ni < 4; ni++) {
        int p = nw * 32 + ni * 8 + (lane & 3) * 2;
        float bb0 = b1[d * A3 + p], bb1 = b1[d * A3 + p + 1];
        float s0 = 0.f, q0 = 0.f, s1 = 0.f, q1 = 0.f;
#pragma unroll
        for (int mi = 0; mi < 2; mi++) {
            int r = mw * 32 + mi * 16 + (lane >> 2);
            float* C = accm[mi][ni];
            float v0 = C[0] + bb0, v1 = C[1] + bb1;
            float v2 = C[2] + bb0, v3 = C[3] + bb1;
            *(float2*)&hb[(size_t)r * A3 + p] = make_float2(v0, v1);
            *(float2*)&hb[(size_t)(r + 8) * A3 + p] = make_float2(v2, v3);
            s0 += v0 + v2; q0 += v0 * v0 + v2 * v2;
            s1 += v1 + v3; q1 += v1 * v1 + v3 * v3;
        }
#pragma unroll
        for (int off = 4; off < 32; off <<= 1) {
            s0 += __shfl_xor_sync(0xffffffffu, s0, off);
            q0 += __shfl_xor_sync(0xffffffffu, q0, off);
            s1 += __shfl_xor_sync(0xffffffffu, s1, off);
            q1 += __shfl_xor_sync(0xffffffffu, q1, off);
        }
        if ((lane >> 2) == 0) {
            atomicAdd(&csum[p], s0); atomicAdd(&csq[p], q0);
            atomicAdd(&csum[p + 1], s1); atomicAdd(&csq[p + 1], q1);
        }
    }
    __syncthreads();
    if (tid < 64) {
        atomicAdd(&g_sum[d * A3 + tid], csum[tid]);
        atomicAdd(&g_sq [d * A3 + tid], csq [tid]);
    }
}

// ---------------- K4: finalize BN -------------------------------------------
__global__ void k4_stats(const float* __restrict__ gamma,
                         const float* __restrict__ beta) {
    int i = threadIdx.x;
    if (i < DTOW * A3) {
        const float inv_n = 1.0f / (float)NROWS;
        float mean = g_sum[i] * inv_n;
        float var  = g_sq[i] * inv_n - mean * mean;
        float is   = rsqrtf(var + 1e-5f);
        float sc   = is * gamma[i];
        g_scale[i] = sc;
        g_shift[i] = beta[i] - mean * sc;
    }
}

// ---------------- K5 (mma): y = elu(bn(h)) @ W2 + b2 -------------------------
// Same canonical machinery; 8 warps = 4(m)x2(n); warp tile 32x48.
__global__ void __launch_bounds__(256) k5_tower2_mma(const float* __restrict__ W2,
                                                     const float* __restrict__ b2) {
    __shared__ uint32_t cA[2][8][2][32][4];    // 16KB
    __shared__ uint32_t cB[2][12][2][32][2];   // 12KB
    __shared__ float sSc[64], sSh[64];
    const int tid = threadIdx.x, wid = tid >> 5, lane = tid & 31;
    const int d = blockIdx.y;
    const int r0 = blockIdx.x * 128;
    const int mw = wid & 3, nw = wid >> 2;

    if (tid < 64) { sSc[tid] = g_scale[d * A3 + tid]; sSh[tid] = g_shift[d * A3 + tid]; }

    float accm[2][6][4];
#pragma unroll
    for (int mi = 0; mi < 2; mi++)
#pragma unroll
        for (int ni = 0; ni < 6; ni++)
#pragma unroll
            for (int j = 0; j < 4; j++) accm[mi][ni][j] = 0.f;

    const float* hbase = g_h + ((size_t)d * NROWS + r0) * A3;
    const float* W2d = W2 + (size_t)d * A3 * PLEN;

    for (int c = 0; c < 2; c++) {
        const int k0 = c * 32;
        __syncthreads();
        // A fill: BN affine + ELU fused, split
#pragma unroll
        for (int it = 0; it < 8; it++) {
            int i = tid + it * 256;
            int r = i >> 4, kp = i & 15;
            int kg = k0 + kp * 2;
            float2 v = *(const float2*)&hbase[(size_t)r * A3 + kg];
            float t0 = fmaf(v.x, sSc[kg], sSh[kg]);
            float t1 = fmaf(v.y, sSc[kg + 1], sSh[kg + 1]);
            t0 = t0 > 0.f ? t0 : expm1f(t0);
            t1 = t1 > 0.f ? t1 : expm1f(t1);
            float h0 = __bfloat162float(__float2bfloat16(t0));
            float h1 = __bfloat162float(__float2bfloat16(t1));
            int ln = (r & 7) * 4 + (kp & 3);
            int rg = ((r >> 3) & 1) | ((kp & 4) >> 1);
            cA[0][r >> 4][kp >> 3][ln][rg] = pack_bf16x2(h0, h1);
            cA[1][r >> 4][kp >> 3][ln][rg] = pack_bf16x2(t0 - h0, t1 - h1);
        }
        // B fill: 96 n x 16 kpairs (W2 is [k][p])
#pragma unroll
        for (int it = 0; it < 6; it++) {
            int i = tid + it * 256;
            int n = i % PLEN, kp = i / PLEN;
            int kg = k0 + kp * 2;
            float w0 = W2d[(size_t)kg * PLEN + n];
            float w1 = W2d[(size_t)(kg + 1) * PLEN + n];
            float h0 = __bfloat162float(__float2bfloat16(w0));
            float h1 = __bfloat162float(__float2bfloat16(w1));
            int ln = (n & 7) * 4 + (kp & 3);
            int rg = (kp & 4) >> 2;
            cB[0][n >> 3][kp >> 3][ln][rg] = pack_bf16x2(h0, h1);
            cB[1][n >> 3][kp >> 3][ln][rg] = pack_bf16x2(w0 - h0, w1 - h1);
        }
        __syncthreads();
#pragma unroll
        for (int tk = 0; tk < 2; tk++) {
            uint32_t ah0[4], ah1[4], al0[4], al1[4];
            *(uint4*)ah0 = *(const uint4*)cA[0][mw * 2 + 0][tk][lane];
            *(uint4*)ah1 = *(const uint4*)cA[0][mw * 2 + 1][tk][lane];
            *(uint4*)al0 = *(const uint4*)cA[1][mw * 2 + 0][tk][lane];
            *(uint4*)al1 = *(const uint4*)cA[1][mw * 2 + 1][tk][lane];
#pragma unroll
            for (int ni = 0; ni < 6; ni++) {
                uint32_t bh[2], bl[2];
                *(uint2*)bh = *(const uint2*)cB[0][nw * 6 + ni][tk][lane];
                *(uint2*)bl = *(const uint2*)cB[1][nw * 6 + ni][tk][lane];
                mma16816(accm[0][ni], ah0, bh);
                mma16816(accm[1][ni], ah1, bh);
                mma16816(accm[0][ni], al0, bh);
                mma16816(accm[1][ni], al1, bh);
                mma16816(accm[0][ni], ah0, bl);
                mma16816(accm[1][ni], ah1, bl);
            }
        }
    }
    // epilogue: +b2, direct float2 stores into row-major g_y
    float* ybase = g_y + ((size_t)d * NROWS + r0) * PLEN;
#pragma unroll
    for (int mi = 0; mi < 2; mi++) {
        int r = mw * 32 + mi * 16 + (lane >> 2);
#pragma unroll
        for (int ni = 0; ni < 6; ni++) {
            int p = nw * 48 + ni * 8 + (lane & 3) * 2;
            float bb0 = b2[d * PLEN + p], bb1 = b2[d * PLEN + p + 1];
            float* C = accm[mi][ni];
            *(float2*)&ybase[(size_t)r * PLEN + p] =
                make_float2(C[0] + bb0, C[1] + bb1);
            *(float2*)&ybase[(size_t)(r + 8) * PLEN + p] =
                make_float2(C[2] + bb0, C[3] + bb1);
        }
    }
}

// ---------------- K6: out[n, p*8+d] = g_y[d][n][p] ---------------------------
__global__ void __launch_bounds__(256) k6_interleave(float* __restrict__ out) {
    const size_t M = (size_t)NROWS * PLEN;
    size_t g = (size_t)blockIdx.x * 256 + threadIdx.x;
    float v[8];
#pragma unroll
    for (int d = 0; d < 8; d++) v[d] = g_y[(size_t)d * M + g];
    float4* o = (float4*)out;
    o[2 * g]     = make_float4(v[0], v[1], v[2], v[3]);
    o[2 * g + 1] = make_float4(v[4], v[5], v[6], v[7]);
}

// ---------------- launch ------------------------------------------------------
extern "C" void kernel_launch(void* const* d_in, const int* in_sizes, int n_in,
                              void* d_out, int out_size) {
    const float* x     = (const float*)d_in[0];
    const float* shu   = (const float*)d_in[1];
    const float* lw    = (const float*)d_in[2];
    const float* lb    = (const float*)d_in[3];
    const float* W1    = (const float*)d_in[4];
    const float* b1    = (const float*)d_in[5];
    const float* gamma = (const float*)d_in[6];
    const float* beta  = (const float*)d_in[7];
    const float* W2    = (const float*)d_in[8];
    const float* b2    = (const float*)d_in[9];
    float* out = (float*)d_out;

    float* rep_out = ((size_t)out_size >= (size_t)NROWS * (PLEN * DTOW + A3))
                         ? out + (size_t)NROWS * PLEN * DTOW
                         : nullptr;

    k1_gemm_norm<<<NROWS / 128, 256>>>(x, shu);
    k2_window<<<NROWS / 128, 256>>>(lw, lb, rep_out);   // also zeros BN accums
    k3_tower1_mma<<<dim3(NROWS / 128, DTOW), 256>>>(W1, b1);
    k4_stats<<<1, 512>>>(gamma, beta);
    k5_tower2_mma<<<dim3(NROWS / 128, DTOW), 256>>>(W2, b2);
    k6_interleave<<<(NROWS * PLEN) / 256, 256>>>(out);
}

// round 11
// speedup vs baseline: 1.6812x; 1.1537x over previous
#include <cuda_runtime.h>
#include <cuda_bf16.h>
#include <math.h>
#include <cstdint>

#define NROWS 65536
#define KDIM  512
#define A3    64
#define CWIN  16
#define DTOW  8
#define PLEN  96

// ---------------- scratch (device globals; no allocations allowed) ----------
__device__ float g_t   [(size_t)NROWS * A3];
__device__ float g_rep [(size_t)NROWS * A3];
__device__ float g_h   [(size_t)DTOW * NROWS * A3];
__device__ float g_y   [(size_t)DTOW * NROWS * PLEN];   // [d][n][p] row-major
__device__ float g_sum[DTOW * A3];
__device__ float g_sq [DTOW * A3];
__device__ float g_scale[DTOW * A3];
__device__ float g_shift[DTOW * A3];

// ---------------- mma.sync helper (HMMA, baseline PTX) -----------------------
__device__ __forceinline__ void mma16816(float* c, const uint32_t* a, const uint32_t* b) {
    asm volatile(
        "mma.sync.aligned.m16n8k16.row.col.f32.bf16.bf16.f32 "
        "{%0,%1,%2,%3}, {%4,%5,%6,%7}, {%8,%9}, {%0,%1,%2,%3};"
        : "+f"(c[0]), "+f"(c[1]), "+f"(c[2]), "+f"(c[3])
        : "r"(a[0]), "r"(a[1]), "r"(a[2]), "r"(a[3]), "r"(b[0]), "r"(b[1]));
}
__device__ __forceinline__ uint32_t pack_bf16x2(float lo, float hi_) {
    __nv_bfloat16 a = __float2bfloat16(lo), b = __float2bfloat16(hi_);
    return ((uint32_t)__bfloat16_as_ushort(b) << 16) | (uint32_t)__bfloat16_as_ushort(a);
}

// ---------------- K1 (mma): t = normalize(x @ shuzhihua) ---------------------
// Same canonical-fragment machinery as k3; 16 K-chunks of 32; normalize epilogue.
__global__ void __launch_bounds__(256) k1_gemm_norm_mma(const float* __restrict__ x,
                                                        const float* __restrict__ w) {
    __shared__ uint32_t cA[2][8][2][32][4];   // 16KB
    __shared__ uint32_t cB[2][8][2][32][2];   //  8KB
    __shared__ float rnorm[128];
    const int tid = threadIdx.x, wid = tid >> 5, lane = tid & 31;
    const int r0 = blockIdx.x * 128;
    const int mw = wid & 3, nw = wid >> 2;

    float accm[2][4][4];
#pragma unroll
    for (int mi = 0; mi < 2; mi++)
#pragma unroll
        for (int ni = 0; ni < 4; ni++)
#pragma unroll
            for (int j = 0; j < 4; j++) accm[mi][ni][j] = 0.f;

    const float* abase = x + (size_t)r0 * KDIM;

    for (int c = 0; c < 16; c++) {
        const int k0 = c * 32;
        __syncthreads();
        // A fill: 128 rows x 16 kpairs of x, hi/lo split
#pragma unroll
        for (int it = 0; it < 8; it++) {
            int i = tid + it * 256;
            int r = i >> 4, kp = i & 15;
            int kg = k0 + kp * 2;
            float2 v = *(const float2*)&abase[(size_t)r * KDIM + kg];
            float h0 = __bfloat162float(__float2bfloat16(v.x));
            float h1 = __bfloat162float(__float2bfloat16(v.y));
            int ln = (r & 7) * 4 + (kp & 3);
            int rg = ((r >> 3) & 1) | ((kp & 4) >> 1);
            cA[0][r >> 4][kp >> 3][ln][rg] = pack_bf16x2(h0, h1);
            cA[1][r >> 4][kp >> 3][ln][rg] = pack_bf16x2(v.x - h0, v.y - h1);
        }
        // B fill: 64 n x 16 kpairs (w is [k][n])
#pragma unroll
        for (int it = 0; it < 4; it++) {
            int i = tid + it * 256;
            int n = i & 63, kp = i >> 6;
            int kg = k0 + kp * 2;
            float w0 = w[(size_t)kg * A3 + n];
            float w1 = w[(size_t)(kg + 1) * A3 + n];
            float h0 = __bfloat162float(__float2bfloat16(w0));
            float h1 = __bfloat162float(__float2bfloat16(w1));
            int ln = (n & 7) * 4 + (kp & 3);
            int rg = (kp & 4) >> 2;
            cB[0][n >> 3][kp >> 3][ln][rg] = pack_bf16x2(h0, h1);
            cB[1][n >> 3][kp >> 3][ln][rg] = pack_bf16x2(w0 - h0, w1 - h1);
        }
        __syncthreads();
#pragma unroll
        for (int tk = 0; tk < 2; tk++) {
            uint32_t ah0[4], ah1[4], al0[4], al1[4];
            *(uint4*)ah0 = *(const uint4*)cA[0][mw * 2 + 0][tk][lane];
            *(uint4*)ah1 = *(const uint4*)cA[0][mw * 2 + 1][tk][lane];
            *(uint4*)al0 = *(const uint4*)cA[1][mw * 2 + 0][tk][lane];
            *(uint4*)al1 = *(const uint4*)cA[1][mw * 2 + 1][tk][lane];
#pragma unroll
            for (int ni = 0; ni < 4; ni++) {
                uint32_t bh[2], bl[2];
                *(uint2*)bh = *(const uint2*)cB[0][nw * 4 + ni][tk][lane];
                *(uint2*)bl = *(const uint2*)cB[1][nw * 4 + ni][tk][lane];
                mma16816(accm[0][ni], ah0, bh);
                mma16816(accm[1][ni], ah1, bh);
                mma16816(accm[0][ni], al0, bh);
                mma16816(accm[1][ni], al1, bh);
                mma16816(accm[0][ni], ah0, bl);
                mma16816(accm[1][ni], ah1, bl);
            }
        }
    }
    // ---- epilogue: row L2 norms then normalized store -----------------------
    if (tid < 128) rnorm[tid] = 0.f;
    __syncthreads();
    // per-thread partials over its 8 cols, 4 rows
    float ssq[4] = {0.f, 0.f, 0.f, 0.f};
#pragma unroll
    for (int mi = 0; mi < 2; mi++)
#pragma unroll
        for (int ni = 0; ni < 4; ni++) {
            float* C = accm[mi][ni];
            ssq[2 * mi + 0] += C[0] * C[0] + C[1] * C[1];
            ssq[2 * mi + 1] += C[2] * C[2] + C[3] * C[3];
        }
    // quad-reduce over lane&3 (same rows, different cols)
#pragma unroll
    for (int off = 1; off < 4; off <<= 1)
#pragma unroll
        for (int j = 0; j < 4; j++)
            ssq[j] += __shfl_xor_sync(0xffffffffu, ssq[j], off);
    if ((lane & 3) == 0) {
        int rb = mw * 32 + (lane >> 2);
        atomicAdd(&rnorm[rb], ssq[0]);
        atomicAdd(&rnorm[rb + 8], ssq[1]);
        atomicAdd(&rnorm[rb + 16], ssq[2]);
        atomicAdd(&rnorm[rb + 24], ssq[3]);
    }
    __syncthreads();
    float* tb = g_t + (size_t)r0 * A3;
#pragma unroll
    for (int mi = 0; mi < 2; mi++) {
        int r = mw * 32 + mi * 16 + (lane >> 2);
        float s0 = 1.f / fmaxf(sqrtf(rnorm[r]), 1e-12f);
        float s1 = 1.f / fmaxf(sqrtf(rnorm[r + 8]), 1e-12f);
#pragma unroll
        for (int ni = 0; ni < 4; ni++) {
            int p = nw * 32 + ni * 8 + (lane & 3) * 2;
            float* C = accm[mi][ni];
            *(float2*)&tb[(size_t)r * A3 + p] = make_float2(C[0] * s0, C[1] * s0);
            *(float2*)&tb[(size_t)(r + 8) * A3 + p] = make_float2(C[2] * s1, C[3] * s1);
        }
    }
}

// ---------------- K2: windowed FIR + BN accum zeroing ------------------------
__global__ void __launch_bounds__(256) k2_window(const float* __restrict__ lw,
                                                 const float* __restrict__ lb,
                                                 float* __restrict__ rep_out) {
    __shared__ float ts[143 * 64];
    __shared__ float lws[16 * 64];
    __shared__ float sb[64];
    const int tid = threadIdx.x;
    const int r0 = blockIdx.x * 128;
    const int base = (r0 >= 15) ? (r0 - 15) : 0;
    const int nrows = r0 + 128 - base;

    if (blockIdx.x == 0) {
        g_sum[tid] = 0.f; g_sq[tid] = 0.f;
        g_sum[tid + 256] = 0.f; g_sq[tid + 256] = 0.f;
    }

    for (int i = tid; i < nrows * 16; i += 256)
        ((float4*)ts)[i] = *(const float4*)&g_t[(size_t)base * A3 + (size_t)i * 4];
    for (int i = tid; i < 256; i += 256)
        ((float4*)lws)[i] = ((const float4*)lw)[i];
    if (tid < 64) {
        float s = 0.f;
#pragma unroll
        for (int j = 0; j < 16; j++) s += lb[j * 64 + tid];
        sb[tid] = s;
    }
    __syncthreads();

    const int c = tid & 63;
    const int rg = tid >> 6;
    float lwr[16];
#pragma unroll
    for (int j = 0; j < 16; j++) lwr[j] = lws[j * 64 + c];
    const float sbc = sb[c];

    for (int rr = 0; rr < 32; rr++) {
        int i = r0 + rg * 32 + rr;
        float accv = sbc;
        if (i >= 15) {
            int off = i - 15 - base;
#pragma unroll
            for (int j = 0; j < 16; j++) accv += lwr[j] * ts[(off + j) * 64 + c];
        } else {
#pragma unroll
            for (int j = 0; j < 16; j++) {
                int s = (j < i) ? j : i;
                accv += lwr[j] * ts[s * 64 + c];
            }
        }
        g_rep[(size_t)i * A3 + c] = accv;
        if (rep_out) rep_out[(size_t)i * A3 + c] = accv;
    }
}

// ---------------- K3 (mma): h = rep @ W1 + b1; BN stats  [R9 form] -----------
__global__ void __launch_bounds__(256) k3_tower1_mma(const float* __restrict__ W1,
                                                     const float* __restrict__ b1) {
    __shared__ uint32_t cA[2][8][2][32][4];
    __shared__ uint32_t cB[2][8][2][32][2];
    __shared__ float csum[64], csq[64];
    const int tid = threadIdx.x, wid = tid >> 5, lane = tid & 31;
    const int d = blockIdx.y;
    const int r0 = blockIdx.x * 128;
    const int mw = wid & 3, nw = wid >> 2;
    if (tid < 64) { csum[tid] = 0.f; csq[tid] = 0.f; }

    float accm[2][4][4];
#pragma unroll
    for (int mi = 0; mi < 2; mi++)
#pragma unroll
        for (int ni = 0; ni < 4; ni++)
#pragma unroll
            for (int j = 0; j < 4; j++) accm[mi][ni][j] = 0.f;

    const float* abase = g_rep + (size_t)r0 * A3;
    const float* W1d = W1 + (size_t)d * A3 * A3;

    for (int c = 0; c < 2; c++) {
        const int k0 = c * 32;
        __syncthreads();
#pragma unroll
        for (int it = 0; it < 8; it++) {
            int i = tid + it * 256;
            int r = i >> 4, kp = i & 15;
            int kg = k0 + kp * 2;
            float2 v = *(const float2*)&abase[(size_t)r * A3 + kg];
            float h0 = __bfloat162float(__float2bfloat16(v.x));
            float h1 = __bfloat162float(__float2bfloat16(v.y));
            int ln = (r & 7) * 4 + (kp & 3);
            int rg = ((r >> 3) & 1) | ((kp & 4) >> 1);
            cA[0][r >> 4][kp >> 3][ln][rg] = pack_bf16x2(h0, h1);
            cA[1][r >> 4][kp >> 3][ln][rg] = pack_bf16x2(v.x - h0, v.y - h1);
        }
#pragma unroll
        for (int it = 0; it < 4; it++) {
            int i = tid + it * 256;
            int n = i & 63, kp = i >> 6;
            int kg = k0 + kp * 2;
            float w0 = W1d[(size_t)kg * A3 + n];
            float w1 = W1d[(size_t)(kg + 1) * A3 + n];
            float h0 = __bfloat162float(__float2bfloat16(w0));
            float h1 = __bfloat162float(__float2bfloat16(w1));
            int ln = (n & 7) * 4 + (kp & 3);
            int rg = (kp & 4) >> 2;
            cB[0][n >> 3][kp >> 3][ln][rg] = pack_bf16x2(h0, h1);
            cB[1][n >> 3][kp >> 3][ln][rg] = pack_bf16x2(w0 - h0, w1 - h1);
        }
        __syncthreads();
#pragma unroll
        for (int tk = 0; tk < 2; tk++) {
            uint32_t ah0[4], ah1[4], al0[4], al1[4];
            *(uint4*)ah0 = *(const uint4*)cA[0][mw * 2 + 0][tk][lane];
            *(uint4*)ah1 = *(const uint4*)cA[0][mw * 2 + 1][tk][lane];
            *(uint4*)al0 = *(const uint4*)cA[1][mw * 2 + 0][tk][lane];
            *(uint4*)al1 = *(const uint4*)cA[1][mw * 2 + 1][tk][lane];
#pragma unroll
            for (int ni = 0; ni < 4; ni++) {
                uint32_t bh[2], bl[2];
                *(uint2*)bh = *(const uint2*)cB[0][nw * 4 + ni][tk][lane];
                *(uint2*)bl = *(const uint2*)cB[1][nw * 4 + ni][tk][lane];
                mma16816(accm[0][ni], ah0, bh);
                mma16816(accm[1][ni], ah1, bh);
                mma16816(accm[0][ni], al0, bh);
                mma16816(accm[1][ni], al1, bh);
                mma16816(accm[0][ni], ah0, bl);
                mma16816(accm[1][ni], ah1, bl);
            }
        }
    }
    float* hb = g_h + ((size_t)d * NROWS + r0) * A3;
#pragma unroll
    for (int ni = 0; ni < 4; ni++) {
        int p = nw * 32 + ni * 8 + (lane & 3) * 2;
        float bb0 = b1[d * A3 + p], bb1 = b1[d * A3 + p + 1];
        float s0 = 0.f, q0 = 0.f, s1 = 0.f, q1 = 0.f;
#pragma unroll
        for (int mi = 0; mi < 2; mi++) {
            int r = mw * 32 + mi * 16 + (lane >> 2);
            float* C = accm[mi][ni];
            float v0 = C[0] + bb0, v1 = C[1] + bb1;
            float v2 = C[2] + bb0, v3 = C[3] + bb1;
            *(float2*)&hb[(size_t)r * A3 + p] = make_float2(v0, v1);
            *(float2*)&hb[(size_t)(r + 8) * A3 + p] = make_float2(v2, v3);
            s0 += v0 + v2; q0 += v0 * v0 + v2 * v2;
            s1 += v1 + v3; q1 += v1 * v1 + v3 * v3;
        }
#pragma unroll
        for (int off = 4; off < 32; off <<= 1) {
            s0 += __shfl_xor_sync(0xffffffffu, s0, off);
            q0 += __shfl_xor_sync(0xffffffffu, q0, off);
            s1 += __shfl_xor_sync(0xffffffffu, s1, off);
            q1 += __shfl_xor_sync(0xffffffffu, q1, off);
        }
        if ((lane >> 2) == 0) {
            atomicAdd(&csum[p], s0); atomicAdd(&csq[p], q0);
            atomicAdd(&csum[p + 1], s1); atomicAdd(&csq[p + 1], q1);
        }
    }
    __syncthreads();
    if (tid < 64) {
        atomicAdd(&g_sum[d * A3 + tid], csum[tid]);
        atomicAdd(&g_sq [d * A3 + tid], csq [tid]);
    }
}

// ---------------- K4: finalize BN -------------------------------------------
__global__ void k4_stats(const float* __restrict__ gamma,
                         const float* __restrict__ beta) {
    int i = threadIdx.x;
    if (i < DTOW * A3) {
        const float inv_n = 1.0f / (float)NROWS;
        float mean = g_sum[i] * inv_n;
        float var  = g_sq[i] * inv_n - mean * mean;
        float is   = rsqrtf(var + 1e-5f);
        float sc   = is * gamma[i];
        g_scale[i] = sc;
        g_shift[i] = beta[i] - mean * sc;
    }
}

// ---------------- K5 (mma): y = elu(bn(h)) @ W2 + b2  [R9 form] --------------
__global__ void __launch_bounds__(256) k5_tower2_mma(const float* __restrict__ W2,
                                                     const float* __restrict__ b2) {
    __shared__ uint32_t cA[2][8][2][32][4];
    __shared__ uint32_t cB[2][12][2][32][2];
    __shared__ float sSc[64], sSh[64];
    const int tid = threadIdx.x, wid = tid >> 5, lane = tid & 31;
    const int d = blockIdx.y;
    const int r0 = blockIdx.x * 128;
    const int mw = wid & 3, nw = wid >> 2;

    if (tid < 64) { sSc[tid] = g_scale[d * A3 + tid]; sSh[tid] = g_shift[d * A3 + tid]; }

    float accm[2][6][4];
#pragma unroll
    for (int mi = 0; mi < 2; mi++)
#pragma unroll
        for (int ni = 0; ni < 6; ni++)
#pragma unroll
            for (int j = 0; j < 4; j++) accm[mi][ni][j] = 0.f;

    const float* hbase = g_h + ((size_t)d * NROWS + r0) * A3;
    const float* W2d = W2 + (size_t)d * A3 * PLEN;

    for (int c = 0; c < 2; c++) {
        const int k0 = c * 32;
        __syncthreads();
#pragma unroll
        for (int it = 0; it < 8; it++) {
            int i = tid + it * 256;
            int r = i >> 4, kp = i & 15;
            int kg = k0 + kp * 2;
            float2 v = *(const float2*)&hbase[(size_t)r * A3 + kg];
            float t0 = fmaf(v.x, sSc[kg], sSh[kg]);
            float t1 = fmaf(v.y, sSc[kg + 1], sSh[kg + 1]);
            t0 = t0 > 0.f ? t0 : expm1f(t0);
            t1 = t1 > 0.f ? t1 : expm1f(t1);
            float h0 = __bfloat162float(__float2bfloat16(t0));
            float h1 = __bfloat162float(__float2bfloat16(t1));
            int ln = (r & 7) * 4 + (kp & 3);
            int rg = ((r >> 3) & 1) | ((kp & 4) >> 1);
            cA[0][r >> 4][kp >> 3][ln][rg] = pack_bf16x2(h0, h1);
            cA[1][r >> 4][kp >> 3][ln][rg] = pack_bf16x2(t0 - h0, t1 - h1);
        }
#pragma unroll
        for (int it = 0; it < 6; it++) {
            int i = tid + it * 256;
            int n = i % PLEN, kp = i / PLEN;
            int kg = k0 + kp * 2;
            float w0 = W2d[(size_t)kg * PLEN + n];
            float w1 = W2d[(size_t)(kg + 1) * PLEN + n];
            float h0 = __bfloat162float(__float2bfloat16(w0));
            float h1 = __bfloat162float(__float2bfloat16(w1));
            int ln = (n & 7) * 4 + (kp & 3);
            int rg = (kp & 4) >> 2;
            cB[0][n >> 3][kp >> 3][ln][rg] = pack_bf16x2(h0, h1);
            cB[1][n >> 3][kp >> 3][ln][rg] = pack_bf16x2(w0 - h0, w1 - h1);
        }
        __syncthreads();
#pragma unroll
        for (int tk = 0; tk < 2; tk++) {
            uint32_t ah0[4], ah1[4], al0[4], al1[4];
            *(uint4*)ah0 = *(const uint4*)cA[0][mw * 2 + 0][tk][lane];
            *(uint4*)ah1 = *(const uint4*)cA[0][mw * 2 + 1][tk][lane];
            *(uint4*)al0 = *(const uint4*)cA[1][mw * 2 + 0][tk][lane];
            *(uint4*)al1 = *(const uint4*)cA[1][mw * 2 + 1][tk][lane];
#pragma unroll
            for (int ni = 0; ni < 6; ni++) {
                uint32_t bh[2], bl[2];
                *(uint2*)bh = *(const uint2*)cB[0][nw * 6 + ni][tk][lane];
                *(uint2*)bl = *(const uint2*)cB[1][nw * 6 + ni][tk][lane];
                mma16816(accm[0][ni], ah0, bh);
                mma16816(accm[1][ni], ah1, bh);
                mma16816(accm[0][ni], al0, bh);
                mma16816(accm[1][ni], al1, bh);
                mma16816(accm[0][ni], ah0, bl);
                mma16816(accm[1][ni], ah1, bl);
            }
        }
    }
    float* ybase = g_y + ((size_t)d * NROWS + r0) * PLEN;
#pragma unroll
    for (int mi = 0; mi < 2; mi++) {
        int r = mw * 32 + mi * 16 + (lane >> 2);
#pragma unroll
        for (int ni = 0; ni < 6; ni++) {
            int p = nw * 48 + ni * 8 + (lane & 3) * 2;
            float bb0 = b2[d * PLEN + p], bb1 = b2[d * PLEN + p + 1];
            float* C = accm[mi][ni];
            *(float2*)&ybase[(size_t)r * PLEN + p] =
                make_float2(C[0] + bb0, C[1] + bb1);
            *(float2*)&ybase[(size_t)(r + 8) * PLEN + p] =
                make_float2(C[2] + bb0, C[3] + bb1);
        }
    }
}

// ---------------- K6: out[n, p*8+d] = g_y[d][n][p] ---------------------------
__global__ void __launch_bounds__(256) k6_interleave(float* __restrict__ out) {
    const size_t M = (size_t)NROWS * PLEN;
    size_t g = (size_t)blockIdx.x * 256 + threadIdx.x;
    float v[8];
#pragma unroll
    for (int d = 0; d < 8; d++) v[d] = g_y[(size_t)d * M + g];
    float4* o = (float4*)out;
    o[2 * g]     = make_float4(v[0], v[1], v[2], v[3]);
    o[2 * g + 1] = make_float4(v[4], v[5], v[6], v[7]);
}

// ---------------- launch ------------------------------------------------------
extern "C" void kernel_launch(void* const* d_in, const int* in_sizes, int n_in,
                              void* d_out, int out_size) {
    const float* x     = (const float*)d_in[0];
    const float* shu   = (const float*)d_in[1];
    const float* lw    = (const float*)d_in[2];
    const float* lb    = (const float*)d_in[3];
    const float* W1    = (const float*)d_in[4];
    const float* b1    = (const float*)d_in[5];
    const float* gamma = (const float*)d_in[6];
    const float* beta  = (const float*)d_in[7];
    const float* W2    = (const float*)d_in[8];
    const float* b2    = (const float*)d_in[9];
    float* out = (float*)d_out;

    float* rep_out = ((size_t)out_size >= (size_t)NROWS * (PLEN * DTOW + A3))
                         ? out + (size_t)NROWS * PLEN * DTOW
                         : nullptr;

    k1_gemm_norm_mma<<<NROWS / 128, 256>>>(x, shu);
    k2_window<<<NROWS / 128, 256>>>(lw, lb, rep_out);   // also zeros BN accums
    k3_tower1_mma<<<dim3(NROWS / 128, DTOW), 256>>>(W1, b1);
    k4_stats<<<1, 512>>>(gamma, beta);
    k5_tower2_mma<<<dim3(NROWS / 128, DTOW), 256>>>(W2, b2);
    k6_interleave<<<(NROWS * PLEN) / 256, 256>>>(out);
}